// round 1
// baseline (speedup 1.0000x reference)
#include <cuda_runtime.h>
#include <math.h>

#define DIMW 128
#define NG   100000
#define TILE 128

// Scratch (no allocations allowed -> __device__ globals)
__device__ float g_pool[(size_t)NG * DIMW];   // segment-sum of silu(feat@W1+b1)
__device__ float g_pool2[(size_t)NG * DIMW];  // pooled after W2
__device__ float g_cnt[NG];                   // atoms per graph
__device__ int   g_is64;                      // batch dtype flag

// ---------------------------------------------------------------------------
// Kernel 0: zero scratch + detect batch dtype (int32 vs int64)
// If batch is int64, word[N-1] is the high word of element (N-1)/2 == 0.
// If batch is int32, word[N-1] is the last (sorted, ~99999) id != 0.
// ---------------------------------------------------------------------------
__global__ void kZero(const int* __restrict__ batch32, int n) {
    size_t i = (size_t)blockIdx.x * blockDim.x + threadIdx.x;
    const size_t poolN = (size_t)NG * DIMW;
    if (i < poolN) g_pool[i] = 0.0f;
    else if (i < poolN + NG) g_cnt[i - poolN] = 0.0f;
    if (i == 0) g_is64 = (batch32[n - 1] == 0) ? 1 : 0;
}

// ---------------------------------------------------------------------------
// Kernel A: per 128-atom tile:
//   - copy feat rows to output (identity passthrough)
//   - s = silu(feat @ W1 + b1)
//   - run-length segment reduce s into g_pool (batch is sorted), count into g_cnt
// ---------------------------------------------------------------------------
__global__ void __launch_bounds__(256, 1) kAtom(
    const float* __restrict__ feat, const void* __restrict__ batch, int n,
    const float* __restrict__ W1, const float* __restrict__ b1,
    float* __restrict__ outFeat)
{
    extern __shared__ float sm[];
    float* sW = sm;                    // 128*128
    float* sA = sm + 128 * 128;        // 128 rows * 132 (pad) -> reused for s
    int*   sG = (int*)(sA + 128 * 132);

    const int t  = threadIdx.x;
    const int a0 = blockIdx.x * TILE;

    // Load W1 (row-major [k][n]) into smem
    const float4* Wv = (const float4*)W1;
    #pragma unroll
    for (int i = t; i < 128 * 32; i += 256) ((float4*)sW)[i] = Wv[i];

    // Load feat tile into smem (row-major, pad stride 132) + passthrough copy
    for (int i = t; i < 128 * 32; i += 256) {
        int m = i >> 5, c = i & 31;
        float4 v = make_float4(0.f, 0.f, 0.f, 0.f);
        int row = a0 + m;
        if (row < n) {
            v = ((const float4*)(feat + (size_t)row * 128))[c];
            ((float4*)(outFeat + (size_t)row * 128))[c] = v;
        }
        ((float4*)(sA + m * 132))[c] = v;
    }
    if (t < 128) {
        int row = a0 + t;
        int g = -1;
        if (row < n)
            g = g_is64 ? (int)((const long long*)batch)[row]
                       : ((const int*)batch)[row];
        sG[t] = g;
    }
    __syncthreads();

    // 8x8 register tile GEMM: acc[i][j] = sum_k featTile[ty*8+i][k] * W1[k][tx*8+j]
    const int ty = t >> 4, tx = t & 15;
    float acc[8][8];
    #pragma unroll
    for (int i = 0; i < 8; i++)
        #pragma unroll
        for (int j = 0; j < 8; j++) acc[i][j] = 0.0f;

    const float* aBase = sA + (ty * 8) * 132;
    #pragma unroll 8
    for (int k = 0; k < 128; ++k) {
        float a[8];
        #pragma unroll
        for (int i = 0; i < 8; i++) a[i] = aBase[i * 132 + k];
        float4 bq0 = *(const float4*)(sW + k * 128 + tx * 8);
        float4 bq1 = *(const float4*)(sW + k * 128 + tx * 8 + 4);
        float b[8] = {bq0.x, bq0.y, bq0.z, bq0.w, bq1.x, bq1.y, bq1.z, bq1.w};
        #pragma unroll
        for (int i = 0; i < 8; i++)
            #pragma unroll
            for (int j = 0; j < 8; j++) acc[i][j] = fmaf(a[i], b[j], acc[i][j]);
    }
    __syncthreads();   // done reading feat tile; reuse sA for s

    // bias + silu, store s into sA
    #pragma unroll
    for (int j = 0; j < 8; j++) {
        float bj = b1[tx * 8 + j];
        #pragma unroll
        for (int i = 0; i < 8; i++) {
            float x = acc[i][j] + bj;
            float s = x / (1.0f + __expf(-x));
            sA[(ty * 8 + i) * 132 + tx * 8 + j] = s;
        }
    }
    __syncthreads();

    // Segment reduce: thread owns dim d over a 64-atom half; batch is sorted
    const int d = t & 127, h = t >> 7;
    const int mS = h * 64, mE = mS + 64;
    float run = 0.0f;
    int   len = 0;
    int   cur = sG[mS];
    for (int m = mS; m < mE; ++m) {
        int g = sG[m];
        if (g != cur) {
            if (cur >= 0) {
                atomicAdd(&g_pool[(size_t)cur * 128 + d], run);
                if (d == 0) atomicAdd(&g_cnt[cur], (float)len);
            }
            run = 0.0f; len = 0; cur = g;
        }
        if (g >= 0) { run += sA[m * 132 + d]; len++; }
    }
    if (cur >= 0) {
        atomicAdd(&g_pool[(size_t)cur * 128 + d], run);
        if (d == 0) atomicAdd(&g_cnt[cur], (float)len);
    }
}

// ---------------------------------------------------------------------------
// Kernel B1: g_pool2 = g_pool @ W2 + cnt * b2     (100K x 128 x 128)
// ---------------------------------------------------------------------------
__global__ void __launch_bounds__(256, 1) kGraph1(
    const float* __restrict__ W2, const float* __restrict__ b2)
{
    extern __shared__ float sm[];
    float* sW = sm;
    float* sA = sm + 128 * 128;
    const int t  = threadIdx.x;
    const int a0 = blockIdx.x * TILE;

    const float4* Wv = (const float4*)W2;
    #pragma unroll
    for (int i = t; i < 128 * 32; i += 256) ((float4*)sW)[i] = Wv[i];
    for (int i = t; i < 128 * 32; i += 256) {
        int m = i >> 5, c = i & 31;
        float4 v = make_float4(0.f, 0.f, 0.f, 0.f);
        int row = a0 + m;
        if (row < NG) v = ((const float4*)(g_pool + (size_t)row * 128))[c];
        ((float4*)(sA + m * 132))[c] = v;
    }
    __syncthreads();

    const int ty = t >> 4, tx = t & 15;
    float acc[8][8];
    #pragma unroll
    for (int i = 0; i < 8; i++)
        #pragma unroll
        for (int j = 0; j < 8; j++) acc[i][j] = 0.0f;

    const float* aBase = sA + (ty * 8) * 132;
    #pragma unroll 8
    for (int k = 0; k < 128; ++k) {
        float a[8];
        #pragma unroll
        for (int i = 0; i < 8; i++) a[i] = aBase[i * 132 + k];
        float4 bq0 = *(const float4*)(sW + k * 128 + tx * 8);
        float4 bq1 = *(const float4*)(sW + k * 128 + tx * 8 + 4);
        float b[8] = {bq0.x, bq0.y, bq0.z, bq0.w, bq1.x, bq1.y, bq1.z, bq1.w};
        #pragma unroll
        for (int i = 0; i < 8; i++)
            #pragma unroll
            for (int j = 0; j < 8; j++) acc[i][j] = fmaf(a[i], b[j], acc[i][j]);
    }

    #pragma unroll
    for (int i = 0; i < 8; i++) {
        int row = a0 + ty * 8 + i;
        if (row < NG) {
            float c = g_cnt[row];
            #pragma unroll
            for (int j = 0; j < 8; j++)
                g_pool2[(size_t)row * 128 + tx * 8 + j] =
                    acc[i][j] + c * b2[tx * 8 + j];
        }
    }
}

// ---------------------------------------------------------------------------
// Kernel B2: out[g] = silu(g_pool2 @ W3 + b3) @ W4 + b4
// ---------------------------------------------------------------------------
__global__ void __launch_bounds__(256, 1) kGraph2(
    const float* __restrict__ W3, const float* __restrict__ b3,
    const float* __restrict__ W4, const float* __restrict__ b4,
    float* __restrict__ outS)
{
    extern __shared__ float sm[];
    float* sW = sm;
    float* sA = sm + 128 * 128;
    float* sV = sA + 128 * 132;  // W4 column (128 floats)
    const int t  = threadIdx.x;
    const int a0 = blockIdx.x * TILE;

    const float4* Wv = (const float4*)W3;
    #pragma unroll
    for (int i = t; i < 128 * 32; i += 256) ((float4*)sW)[i] = Wv[i];
    for (int i = t; i < 128 * 32; i += 256) {
        int m = i >> 5, c = i & 31;
        float4 v = make_float4(0.f, 0.f, 0.f, 0.f);
        int row = a0 + m;
        if (row < NG) v = ((const float4*)(g_pool2 + (size_t)row * 128))[c];
        ((float4*)(sA + m * 132))[c] = v;
    }
    if (t < 128) sV[t] = W4[t];
    __syncthreads();

    const int ty = t >> 4, tx = t & 15;
    float acc[8][8];
    #pragma unroll
    for (int i = 0; i < 8; i++)
        #pragma unroll
        for (int j = 0; j < 8; j++) acc[i][j] = 0.0f;

    const float* aBase = sA + (ty * 8) * 132;
    #pragma unroll 8
    for (int k = 0; k < 128; ++k) {
        float a[8];
        #pragma unroll
        for (int i = 0; i < 8; i++) a[i] = aBase[i * 132 + k];
        float4 bq0 = *(const float4*)(sW + k * 128 + tx * 8);
        float4 bq1 = *(const float4*)(sW + k * 128 + tx * 8 + 4);
        float b[8] = {bq0.x, bq0.y, bq0.z, bq0.w, bq1.x, bq1.y, bq1.z, bq1.w};
        #pragma unroll
        for (int i = 0; i < 8; i++)
            #pragma unroll
            for (int j = 0; j < 8; j++) acc[i][j] = fmaf(a[i], b[j], acc[i][j]);
    }
    __syncthreads();   // done reading pooled tile; reuse sA for q

    #pragma unroll
    for (int j = 0; j < 8; j++) {
        float bj = b3[tx * 8 + j];
        #pragma unroll
        for (int i = 0; i < 8; i++) {
            float x = acc[i][j] + bj;
            float s = x / (1.0f + __expf(-x));
            sA[(ty * 8 + i) * 132 + tx * 8 + j] = s;
        }
    }
    __syncthreads();

    if (t < 128) {
        int row = a0 + t;
        if (row < NG) {
            float s = 0.0f;
            #pragma unroll 8
            for (int k2 = 0; k2 < 128; ++k2) s = fmaf(sA[t * 132 + k2], sV[k2], s);
            outS[row] = s + b4[0];
        }
    }
}

// ---------------------------------------------------------------------------
// Launch
// Inputs: feat, batch, W1, b1, W2, b2, W3, b3, W4, b4
// Output: [ out (NG*1) | feat passthrough (n*128) ]
// ---------------------------------------------------------------------------
extern "C" void kernel_launch(void* const* d_in, const int* in_sizes, int n_in,
                              void* d_out, int out_size)
{
    const float* feat  = (const float*)d_in[0];
    const void*  batch = d_in[1];
    const float* W1 = (const float*)d_in[2];
    const float* b1 = (const float*)d_in[3];
    const float* W2 = (const float*)d_in[4];
    const float* b2 = (const float*)d_in[5];
    const float* W3 = (const float*)d_in[6];
    const float* b3 = (const float*)d_in[7];
    const float* W4 = (const float*)d_in[8];
    const float* b4 = (const float*)d_in[9];

    const int n = in_sizes[0] / DIMW;  // atoms
    float* outS    = (float*)d_out;
    float* outFeat = (float*)d_out + NG;  // NUM_GRAPHS * NUM_OUT

    const size_t smemB = (size_t)(128 * 128 + 128 * 132 + 128 + 128) * 4;

    cudaFuncSetAttribute(kAtom,   cudaFuncAttributeMaxDynamicSharedMemorySize, (int)smemB);
    cudaFuncSetAttribute(kGraph1, cudaFuncAttributeMaxDynamicSharedMemorySize, (int)smemB);
    cudaFuncSetAttribute(kGraph2, cudaFuncAttributeMaxDynamicSharedMemorySize, (int)smemB);

    {
        size_t total = (size_t)NG * DIMW + NG;
        int grid = (int)((total + 255) / 256);
        kZero<<<grid, 256>>>((const int*)batch, n);
    }
    {
        int grid = (n + TILE - 1) / TILE;
        kAtom<<<grid, 256, smemB>>>(feat, batch, n, W1, b1, outFeat);
    }
    {
        int grid = (NG + TILE - 1) / TILE;
        kGraph1<<<grid, 256, smemB>>>(W2, b2);
        kGraph2<<<grid, 256, smemB>>>(W3, b3, W4, b4, outS);
    }
}

// round 3
// speedup vs baseline: 1.6721x; 1.6721x over previous
#include <cuda_runtime.h>
#include <cuda_bf16.h>
#include <math.h>
#include <stdint.h>

#define DIMW 128
#define NG   100000
#define AS_B 272              // bytes per bf16 row (128*2 + 16 pad)

// ---------------- scratch (no allocs) ----------------
__device__ float g_pool[(size_t)NG * DIMW];
__device__ float g_pool2[(size_t)NG * DIMW];
__device__ float g_cnt[NG];
__device__ int   g_is64;
__device__ __nv_bfloat16 g_WTh[3 * 128 * 128];  // W{1,2,3}^T hi  [n][k]
__device__ __nv_bfloat16 g_WTl[3 * 128 * 128];  // lo

// ---------------- kAtom smem layout (bytes) ----------------
#define SM_SG    0             // int[2][128]
#define SM_B1    1024          // float[128]
#define SM_W     2048          // Whi 34816, Wlo 34816
#define SM_BUF0  71680         // Ah 34816 + Al 34816
#define SM_BUF1  141312
#define SMEM_ATOM 210944

// ---------------- kGraph smem layout ----------------
#define GS_MISC  0             // cnt/sV 512B + bias 512B
#define GS_W     1024
#define GS_A     70656
#define SMEM_GRAPH 140288

__device__ __forceinline__ uint32_t smem_u32(const void* p) {
    uint32_t a;
    asm("{ .reg .u64 t; cvta.to.shared.u64 t, %1; cvt.u32.u64 %0, t; }" : "=r"(a) : "l"(p));
    return a;
}
__device__ __forceinline__ void ldsm4(uint32_t& r0, uint32_t& r1, uint32_t& r2, uint32_t& r3,
                                      uint32_t addr) {
    asm volatile("ldmatrix.sync.aligned.m8n8.x4.shared.b16 {%0,%1,%2,%3}, [%4];"
                 : "=r"(r0), "=r"(r1), "=r"(r2), "=r"(r3) : "r"(addr));
}
__device__ __forceinline__ void mma16816(float* c, uint32_t a0, uint32_t a1, uint32_t a2,
                                         uint32_t a3, uint32_t b0, uint32_t b1) {
    asm volatile("mma.sync.aligned.m16n8k16.row.col.f32.bf16.bf16.f32 "
                 "{%0,%1,%2,%3}, {%4,%5,%6,%7}, {%8,%9}, {%0,%1,%2,%3};"
                 : "+f"(c[0]), "+f"(c[1]), "+f"(c[2]), "+f"(c[3])
                 : "r"(a0), "r"(a1), "r"(a2), "r"(a3), "r"(b0), "r"(b1));
}

// ---------------------------------------------------------------------------
// Shared 3-pass bf16-split GEMM: acc[16][4] += Atile(128x128) @ Wtile^T
// Warp w computes rows m0=16w..16w+15, all 128 cols. Padded rows (272B).
// ---------------------------------------------------------------------------
__device__ __forceinline__ void mma_3pass(uint32_t aHi, uint32_t aLo,
                                          uint32_t wHi, uint32_t wLo,
                                          float acc[16][4], int m0) {
    const int lane = threadIdx.x & 31;
    const int lm = lane & 7, q = lane >> 3;
    // A: quad0 (m0,k0) quad1 (m0+8,k0) quad2 (m0,k8) quad3 (m0+8,k8)
    const uint32_t aRowOff = (uint32_t)((m0 + lm + (q & 1) * 8) * AS_B + ((q >> 1) * 8) * 2);
    // B: quad0 (n0,k0) quad1 (n0,k8) quad2 (n0+8,k0) quad3 (n0+8,k8)
    const uint32_t bRowOff = (uint32_t)((lm + (q >> 1) * 8) * AS_B + ((q & 1) * 8) * 2);

    #pragma unroll
    for (int p = 0; p < 3; p++) {
        const uint32_t Ab = (p == 1 ? aLo : aHi) + aRowOff;
        const uint32_t Bb = (p == 2 ? wLo : wHi) + bRowOff;
        #pragma unroll
        for (int kk = 0; kk < 8; kk++) {
            uint32_t a0, a1, a2, a3;
            ldsm4(a0, a1, a2, a3, Ab + kk * 32);
            #pragma unroll
            for (int nb = 0; nb < 8; nb++) {
                uint32_t b0, b1, b2, b3;
                ldsm4(b0, b1, b2, b3, Bb + nb * 16 * AS_B + kk * 32);
                mma16816(acc[nb * 2 + 0], a0, a1, a2, a3, b0, b1);
                mma16816(acc[nb * 2 + 1], a0, a1, a2, a3, b2, b3);
            }
        }
    }
}

// Copy one prepped weight matrix (dense [n][k]) into padded smem hi/lo
__device__ __forceinline__ void stage_W(char* sm, uint32_t wOff, int widx, int t) {
    const int r = t & 127, half = t >> 7;
    const uint4* wh = (const uint4*)(g_WTh + widx * 16384 + r * 128 + half * 64);
    const uint4* wl = (const uint4*)(g_WTl + widx * 16384 + r * 128 + half * 64);
    char* dh = sm + wOff + r * AS_B + half * 128;
    char* dl = sm + wOff + 34816 + r * AS_B + half * 128;
    #pragma unroll
    for (int qq = 0; qq < 8; qq++) {
        ((uint4*)dh)[qq] = wh[qq];
        ((uint4*)dl)[qq] = wl[qq];
    }
}

// Convert 16 float4 (rows m=(t>>5)+8j, col c=t&31) into bf16 hi/lo padded smem
__device__ __forceinline__ void store_A(const float4* v, char* dstH, int t) {
    const int c = t & 31, mb = t >> 5;
    char* dstL = dstH + 34816;
    #pragma unroll
    for (int j = 0; j < 16; j++) {
        const int m = mb + j * 8;
        float4 x = v[j];
        __nv_bfloat16 h0 = __float2bfloat16_rn(x.x), h1 = __float2bfloat16_rn(x.y);
        __nv_bfloat16 h2 = __float2bfloat16_rn(x.z), h3 = __float2bfloat16_rn(x.w);
        __nv_bfloat162 hp0 = __halves2bfloat162(h0, h1);
        __nv_bfloat162 hp1 = __halves2bfloat162(h2, h3);
        __nv_bfloat162 lp0 = __halves2bfloat162(
            __float2bfloat16_rn(x.x - __bfloat162float(h0)),
            __float2bfloat16_rn(x.y - __bfloat162float(h1)));
        __nv_bfloat162 lp1 = __halves2bfloat162(
            __float2bfloat16_rn(x.z - __bfloat162float(h2)),
            __float2bfloat16_rn(x.w - __bfloat162float(h3)));
        uint2 H = make_uint2(*(uint32_t*)&hp0, *(uint32_t*)&hp1);
        uint2 L = make_uint2(*(uint32_t*)&lp0, *(uint32_t*)&lp1);
        *(uint2*)(dstH + m * AS_B + c * 8) = H;
        *(uint2*)(dstL + m * AS_B + c * 8) = L;
    }
}

// ---------------------------------------------------------------------------
__global__ void kZero(const int* __restrict__ batch32, int n) {
    size_t i = (size_t)blockIdx.x * blockDim.x + threadIdx.x;
    const size_t poolN = (size_t)NG * DIMW;
    if (i < poolN) g_pool[i] = 0.0f;
    else if (i < poolN + NG) g_cnt[i - poolN] = 0.0f;
    if (i == 0) g_is64 = (batch32[n - 1] == 0) ? 1 : 0;
}

__global__ void kPrep(const float* __restrict__ W1, const float* __restrict__ W2,
                      const float* __restrict__ W3) {
    int i = blockIdx.x * 256 + threadIdx.x;
    if (i < 3 * 16384) {
        int widx = i >> 14, e = i & 16383;
        int nn = e >> 7, kk = e & 127;
        const float* W = (widx == 0) ? W1 : (widx == 1) ? W2 : W3;
        float w = W[kk * 128 + nn];
        __nv_bfloat16 h = __float2bfloat16_rn(w);
        g_WTh[i] = h;
        g_WTl[i] = __float2bfloat16_rn(w - __bfloat162float(h));
    }
}

// ---------------------------------------------------------------------------
// kAtomTC: persistent; s = silu(feat@W1+b1) -> segment reduce; feat passthrough
// ---------------------------------------------------------------------------
__global__ void __launch_bounds__(256, 1) kAtomTC(
    const float* __restrict__ feat, const void* __restrict__ batch, int n,
    const float* __restrict__ b1, float* __restrict__ outFeat, int ntiles)
{
    extern __shared__ char sm[];
    const uint32_t smb = smem_u32(sm);
    const int t = threadIdx.x, w = t >> 5, lane = t & 31;
    const int is64 = g_is64;

    if (t < 128) ((float*)(sm + SM_B1))[t] = b1[t];
    stage_W(sm, SM_W, 0, t);

    const int per = (ntiles + gridDim.x - 1) / gridDim.x;
    const int t0 = blockIdx.x * per;
    const int t1 = min(t0 + per, ntiles);
    if (t0 >= t1) return;

    const int c = t & 31, mb = t >> 5;

    // prologue: load + store tile t0 into buf0
    {
        float4 v[16];
        #pragma unroll
        for (int j = 0; j < 16; j++) {
            long long row = (long long)t0 * 128 + mb + j * 8;
            v[j] = (row < n) ? ((const float4*)(feat + row * 128))[c]
                             : make_float4(0.f, 0.f, 0.f, 0.f);
            if (row < n) ((float4*)(outFeat + row * 128))[c] = v[j];
        }
        store_A(v, sm + SM_BUF0, t);
        if (t < 128) {
            long long row = (long long)t0 * 128 + t;
            int g = -1;
            if (row < n)
                g = is64 ? (int)((const long long*)batch)[row] : ((const int*)batch)[row];
            ((int*)(sm + SM_SG))[t] = g;
        }
    }

    for (int i = t0; i < t1; ++i) {
        const int buf = (i - t0) & 1;
        const uint32_t bufOff = buf ? SM_BUF1 : SM_BUF0;
        const uint32_t nbufOff = buf ? SM_BUF0 : SM_BUF1;
        const bool more = (i + 1 < t1);

        // issue next-tile LDGs early
        float4 v[16];
        if (more) {
            #pragma unroll
            for (int j = 0; j < 16; j++) {
                long long row = (long long)(i + 1) * 128 + mb + j * 8;
                v[j] = (row < n) ? ((const float4*)(feat + row * 128))[c]
                                 : make_float4(0.f, 0.f, 0.f, 0.f);
            }
        }

        __syncthreads();   // A(buf) visible

        float acc[16][4];
        #pragma unroll
        for (int a = 0; a < 16; a++)
            #pragma unroll
            for (int b = 0; b < 4; b++) acc[a][b] = 0.0f;
        mma_3pass(smb + bufOff, smb + bufOff + 34816,
                  smb + SM_W, smb + SM_W + 34816, acc, w * 16);

        __syncthreads();   // all warps done reading A(buf)

        // epilogue: bias + silu -> transposed staging sT (stride 129) over buf
        float* sT = (float*)(sm + bufOff);
        const float* sB1 = (const float*)(sm + SM_B1);
        const int m0 = w * 16;
        #pragma unroll
        for (int nt = 0; nt < 16; nt++) {
            const int n0 = (nt >> 1) * 16 + (nt & 1) * 8 + (lane & 3) * 2;
            const int mr = m0 + (lane >> 2);
            #pragma unroll
            for (int j = 0; j < 4; j++) {
                const int nn = n0 + (j & 1);
                const int mm = mr + ((j >> 1) ? 8 : 0);
                float x = acc[nt][j] + sB1[nn];
                sT[nn * 129 + mm] = x / (1.0f + __expf(-x));
            }
        }

        // store next tile + passthrough + batch ids
        if (more) {
            #pragma unroll
            for (int j = 0; j < 16; j++) {
                long long row = (long long)(i + 1) * 128 + mb + j * 8;
                if (row < n) ((float4*)(outFeat + row * 128))[c] = v[j];
            }
            store_A(v, sm + nbufOff, t);
            if (t < 128) {
                long long row = (long long)(i + 1) * 128 + t;
                int g = -1;
                if (row < n)
                    g = is64 ? (int)((const long long*)batch)[row] : ((const int*)batch)[row];
                ((int*)(sm + SM_SG))[(buf ^ 1) * 128 + t] = g;
            }
        }

        __syncthreads();   // sT + sG visible

        // run-length segment reduce (batch sorted)
        const int d = t & 127, hh = t >> 7;
        const int mS = hh * 64, mE = mS + 64;
        const int* gid = (const int*)(sm + SM_SG) + buf * 128;
        float run = 0.0f;
        int len = 0, cur = gid[mS];
        for (int mm = mS; mm < mE; ++mm) {
            int g = gid[mm];
            if (g != cur) {
                if (cur >= 0) {
                    atomicAdd(&g_pool[(size_t)cur * 128 + d], run);
                    if (d == 0) atomicAdd(&g_cnt[cur], (float)len);
                }
                run = 0.0f; len = 0; cur = g;
            }
            if (g >= 0) { run += sT[d * 129 + mm]; len++; }
        }
        if (cur >= 0) {
            atomicAdd(&g_pool[(size_t)cur * 128 + d], run);
            if (d == 0) atomicAdd(&g_cnt[cur], (float)len);
        }
    }
}

// ---------------------------------------------------------------------------
// kGraph1: g_pool2 = g_pool @ W2 + cnt * b2
// ---------------------------------------------------------------------------
__global__ void __launch_bounds__(256, 1) kGraph1(const float* __restrict__ b2)
{
    extern __shared__ char sm[];
    const uint32_t smb = smem_u32(sm);
    const int t = threadIdx.x, w = t >> 5, lane = t & 31;
    const int a0 = blockIdx.x * 128;
    const int c = t & 31, mb = t >> 5;

    float* sCnt = (float*)(sm + GS_MISC);
    float* sB   = (float*)(sm + GS_MISC + 512);
    if (t < 128) {
        sCnt[t] = (a0 + t < NG) ? g_cnt[a0 + t] : 0.0f;
        sB[t] = b2[t];
    }
    stage_W(sm, GS_W, 1, t);
    {
        float4 v[16];
        #pragma unroll
        for (int j = 0; j < 16; j++) {
            int row = a0 + mb + j * 8;
            v[j] = (row < NG) ? ((const float4*)(g_pool + (size_t)row * 128))[c]
                              : make_float4(0.f, 0.f, 0.f, 0.f);
        }
        store_A(v, sm + GS_A, t);
    }
    __syncthreads();

    float acc[16][4];
    #pragma unroll
    for (int a = 0; a < 16; a++)
        #pragma unroll
        for (int b = 0; b < 4; b++) acc[a][b] = 0.0f;
    mma_3pass(smb + GS_A, smb + GS_A + 34816, smb + GS_W, smb + GS_W + 34816, acc, w * 16);

    const int m0 = w * 16;
    #pragma unroll
    for (int nt = 0; nt < 16; nt++) {
        const int n0 = (nt >> 1) * 16 + (nt & 1) * 8 + (lane & 3) * 2;
        const int mr = m0 + (lane >> 2);
        int row0 = a0 + mr, row1 = a0 + mr + 8;
        if (row0 < NG) {
            float cn = sCnt[mr];
            float2 o = make_float2(acc[nt][0] + cn * sB[n0], acc[nt][1] + cn * sB[n0 + 1]);
            *(float2*)(g_pool2 + (size_t)row0 * 128 + n0) = o;
        }
        if (row1 < NG) {
            float cn = sCnt[mr + 8];
            float2 o = make_float2(acc[nt][2] + cn * sB[n0], acc[nt][3] + cn * sB[n0 + 1]);
            *(float2*)(g_pool2 + (size_t)row1 * 128 + n0) = o;
        }
    }
}

// ---------------------------------------------------------------------------
// kGraph2: out = silu(g_pool2 @ W3 + b3) @ W4 + b4
// ---------------------------------------------------------------------------
__global__ void __launch_bounds__(256, 1) kGraph2(
    const float* __restrict__ b3, const float* __restrict__ W4,
    const float* __restrict__ b4, float* __restrict__ outS)
{
    extern __shared__ char sm[];
    const uint32_t smb = smem_u32(sm);
    const int t = threadIdx.x, w = t >> 5, lane = t & 31;
    const int a0 = blockIdx.x * 128;
    const int c = t & 31, mb = t >> 5;

    float* sV = (float*)(sm + GS_MISC);
    float* sB = (float*)(sm + GS_MISC + 512);
    if (t < 128) { sV[t] = W4[t]; sB[t] = b3[t]; }
    stage_W(sm, GS_W, 2, t);
    {
        float4 v[16];
        #pragma unroll
        for (int j = 0; j < 16; j++) {
            int row = a0 + mb + j * 8;
            v[j] = (row < NG) ? ((const float4*)(g_pool2 + (size_t)row * 128))[c]
                              : make_float4(0.f, 0.f, 0.f, 0.f);
        }
        store_A(v, sm + GS_A, t);
    }
    __syncthreads();

    float acc[16][4];
    #pragma unroll
    for (int a = 0; a < 16; a++)
        #pragma unroll
        for (int b = 0; b < 4; b++) acc[a][b] = 0.0f;
    mma_3pass(smb + GS_A, smb + GS_A + 34816, smb + GS_W, smb + GS_W + 34816, acc, w * 16);

    float s0 = 0.0f, s1 = 0.0f;
    const int m0 = w * 16;
    #pragma unroll
    for (int nt = 0; nt < 16; nt++) {
        const int n0 = (nt >> 1) * 16 + (nt & 1) * 8 + (lane & 3) * 2;
        #pragma unroll
        for (int j = 0; j < 4; j++) {
            const int nn = n0 + (j & 1);
            float x = acc[nt][j] + sB[nn];
            float h = x / (1.0f + __expf(-x));
            float p = h * sV[nn];
            if (j < 2) s0 += p; else s1 += p;
        }
    }
    s0 += __shfl_xor_sync(0xFFFFFFFF, s0, 1);
    s0 += __shfl_xor_sync(0xFFFFFFFF, s0, 2);
    s1 += __shfl_xor_sync(0xFFFFFFFF, s1, 1);
    s1 += __shfl_xor_sync(0xFFFFFFFF, s1, 2);
    if ((lane & 3) == 0) {
        float b4v = b4[0];
        int row0 = a0 + m0 + (lane >> 2);
        int row1 = row0 + 8;
        if (row0 < NG) outS[row0] = s0 + b4v;
        if (row1 < NG) outS[row1] = s1 + b4v;
    }
}

// ---------------------------------------------------------------------------
extern "C" void kernel_launch(void* const* d_in, const int* in_sizes, int n_in,
                              void* d_out, int out_size)
{
    const float* feat  = (const float*)d_in[0];
    const void*  batch = d_in[1];
    const float* W1 = (const float*)d_in[2];
    const float* b1 = (const float*)d_in[3];
    const float* W2 = (const float*)d_in[4];
    const float* b2 = (const float*)d_in[5];
    const float* W3 = (const float*)d_in[6];
    const float* b3 = (const float*)d_in[7];
    const float* W4 = (const float*)d_in[8];
    const float* b4 = (const float*)d_in[9];

    const int n = in_sizes[0] / DIMW;
    float* outS    = (float*)d_out;
    float* outFeat = (float*)d_out + NG;

    cudaFuncSetAttribute(kAtomTC, cudaFuncAttributeMaxDynamicSharedMemorySize, SMEM_ATOM);
    cudaFuncSetAttribute(kGraph1, cudaFuncAttributeMaxDynamicSharedMemorySize, SMEM_GRAPH);
    cudaFuncSetAttribute(kGraph2, cudaFuncAttributeMaxDynamicSharedMemorySize, SMEM_GRAPH);

    {
        size_t total = (size_t)NG * DIMW + NG;
        kZero<<<(int)((total + 255) / 256), 256>>>((const int*)batch, n);
    }
    kPrep<<<192, 256>>>(W1, W2, W3);
    {
        int ntiles = (n + 127) / 128;
        kAtomTC<<<148, 256, SMEM_ATOM>>>(feat, batch, n, b1, outFeat, ntiles);
    }
    {
        int grid = (NG + 127) / 128;
        kGraph1<<<grid, 256, SMEM_GRAPH>>>(b2);
        kGraph2<<<grid, 256, SMEM_GRAPH>>>(b3, W4, b4, outS);
    }
}

// round 4
// speedup vs baseline: 1.9274x; 1.1527x over previous
#include <cuda_runtime.h>
#include <cuda_bf16.h>
#include <math.h>
#include <stdint.h>

#define DIMW 128
#define NG   100000
#define AS_B 272              // bytes per bf16 row (128*2 + 16 pad)

// ---------------- scratch (no allocs) ----------------
__device__ float g_pool[(size_t)NG * DIMW];
__device__ float g_pool2[(size_t)NG * DIMW];
__device__ float g_cnt[NG];
__device__ int   g_is64;
__device__ __nv_bfloat16 g_WTh[3 * 128 * 128];  // W{1,2,3}^T hi  [n][k]
__device__ __nv_bfloat16 g_WTl[3 * 128 * 128];  // lo

// ---------------- kAtom smem layout (bytes) ----------------
#define SM_GID   0             // int[128]
#define SM_B1    512           // float[128]
#define SM_W     1024          // Wh 34816 + Wl 34816 -> ends 70656
#define SM_A     70656         // Ah 34816 + Al 34816 -> ends 140288 (sT reuses)
#define SM_STAGE 140288        // fp32 tile 65536 -> ends 205824
#define SMEM_ATOM 205824

// ---------------- kGraph smem layout ----------------
#define GS_C     0             // cnt / sV : 512B
#define GS_B     512           // bias     : 512B
#define GS_P     1024          // partials : 1024B
#define GS_W     2048          // 69632 -> ends 71680
#define GS_A     71680         // 69632 -> ends 141312
#define SMEM_GRAPH 141312

__device__ __forceinline__ uint32_t smem_u32(const void* p) {
    uint32_t a;
    asm("{ .reg .u64 t; cvta.to.shared.u64 t, %1; cvt.u32.u64 %0, t; }" : "=r"(a) : "l"(p));
    return a;
}
__device__ __forceinline__ void ldsm4(uint32_t& r0, uint32_t& r1, uint32_t& r2, uint32_t& r3,
                                      uint32_t addr) {
    asm volatile("ldmatrix.sync.aligned.m8n8.x4.shared.b16 {%0,%1,%2,%3}, [%4];"
                 : "=r"(r0), "=r"(r1), "=r"(r2), "=r"(r3) : "r"(addr));
}
__device__ __forceinline__ void mma16816(float* c, uint32_t a0, uint32_t a1, uint32_t a2,
                                         uint32_t a3, uint32_t b0, uint32_t b1) {
    asm volatile("mma.sync.aligned.m16n8k16.row.col.f32.bf16.bf16.f32 "
                 "{%0,%1,%2,%3}, {%4,%5,%6,%7}, {%8,%9}, {%0,%1,%2,%3};"
                 : "+f"(c[0]), "+f"(c[1]), "+f"(c[2]), "+f"(c[3])
                 : "r"(a0), "r"(a1), "r"(a2), "r"(a3), "r"(b0), "r"(b1));
}
__device__ __forceinline__ void cp16(uint32_t dst, const void* src, int sz) {
    asm volatile("cp.async.ca.shared.global [%0], [%1], 16, %2;"
                 :: "r"(dst), "l"(src), "r"(sz) : "memory");
}
__device__ __forceinline__ void cp_commit() { asm volatile("cp.async.commit_group;" ::: "memory"); }
__device__ __forceinline__ void cp_wait0()  { asm volatile("cp.async.wait_group 0;"  ::: "memory"); }

// ---------------------------------------------------------------------------
// Warp-tile core: 16 rows x 64 cols, 3-pass bf16 split.
// 16 warps cover 128x128: wm = w>>1 (rows), wn = w&1 (cols).
// ---------------------------------------------------------------------------
__device__ __forceinline__ void lda_frags(uint32_t a[8][4], uint32_t Ab) {
    #pragma unroll
    for (int kk = 0; kk < 8; kk++)
        ldsm4(a[kk][0], a[kk][1], a[kk][2], a[kk][3], Ab + kk * 32);
}
__device__ __forceinline__ void mma_inner(const uint32_t a[8][4], uint32_t Bb,
                                          float acc[4][8]) {
    #pragma unroll
    for (int nb = 0; nb < 4; nb++) {
        #pragma unroll
        for (int kk = 0; kk < 8; kk++) {
            uint32_t b0, b1, b2, b3;
            ldsm4(b0, b1, b2, b3, Bb + nb * 16 * AS_B + kk * 32);
            mma16816(acc[nb],     a[kk][0], a[kk][1], a[kk][2], a[kk][3], b0, b1);
            mma16816(acc[nb] + 4, a[kk][0], a[kk][1], a[kk][2], a[kk][3], b2, b3);
        }
    }
}
// full 3-pass: acc += A @ W^T  for this warp's 16x64 sub-tile
__device__ __forceinline__ void mma_3pass(uint32_t aHi, uint32_t aLo,
                                          uint32_t wHi, uint32_t wLo,
                                          float acc[4][8]) {
    const int t = threadIdx.x;
    const int w = t >> 5, lane = t & 31;
    const int wm = w >> 1, wn = w & 1;
    const int lm = lane & 7, q = lane >> 3;
    const uint32_t aOff = (uint32_t)((wm * 16 + lm + (q & 1) * 8) * AS_B + ((q >> 1) * 8) * 2);
    const uint32_t bOff = (uint32_t)((wn * 64 + lm + (q >> 1) * 8) * AS_B + ((q & 1) * 8) * 2);
    uint32_t a[8][4];
    lda_frags(a, aHi + aOff);
    mma_inner(a, wHi + bOff, acc);   // Ah * Bh
    mma_inner(a, wLo + bOff, acc);   // Ah * Bl
    lda_frags(a, aLo + aOff);
    mma_inner(a, wHi + bOff, acc);   // Al * Bh
}

// stage one prepped weight matrix into padded smem hi/lo (512 threads)
__device__ __forceinline__ void stage_W(char* sm, uint32_t wOff, int widx, int t) {
    const int r = t >> 2, q = t & 3;
    const uint4* wh = (const uint4*)(g_WTh + widx * 16384 + r * 128 + q * 32);
    const uint4* wl = (const uint4*)(g_WTl + widx * 16384 + r * 128 + q * 32);
    char* dh = sm + wOff + r * AS_B + q * 64;
    char* dl = sm + wOff + 34816 + r * AS_B + q * 64;
    #pragma unroll
    for (int j = 0; j < 4; j++) {
        ((uint4*)dh)[j] = wh[j];
        ((uint4*)dl)[j] = wl[j];
    }
}

// split one fp32 float4 into bf16 hi/lo and store at (row m, float-col c*4)
__device__ __forceinline__ void split_store(float4 x, char* dstH, int m, int c) {
    __nv_bfloat16 h0 = __float2bfloat16_rn(x.x), h1 = __float2bfloat16_rn(x.y);
    __nv_bfloat16 h2 = __float2bfloat16_rn(x.z), h3 = __float2bfloat16_rn(x.w);
    __nv_bfloat162 hp0 = __halves2bfloat162(h0, h1);
    __nv_bfloat162 hp1 = __halves2bfloat162(h2, h3);
    __nv_bfloat162 lp0 = __halves2bfloat162(
        __float2bfloat16_rn(x.x - __bfloat162float(h0)),
        __float2bfloat16_rn(x.y - __bfloat162float(h1)));
    __nv_bfloat162 lp1 = __halves2bfloat162(
        __float2bfloat16_rn(x.z - __bfloat162float(h2)),
        __float2bfloat16_rn(x.w - __bfloat162float(h3)));
    *(uint2*)(dstH + m * AS_B + c * 8) = make_uint2(*(uint32_t*)&hp0, *(uint32_t*)&hp1);
    *(uint2*)(dstH + 34816 + m * AS_B + c * 8) = make_uint2(*(uint32_t*)&lp0, *(uint32_t*)&lp1);
}

// ---------------------------------------------------------------------------
__global__ void kZero(const int* __restrict__ batch32, int n) {
    size_t i = (size_t)blockIdx.x * blockDim.x + threadIdx.x;
    const size_t poolN = (size_t)NG * DIMW;
    if (i < poolN) g_pool[i] = 0.0f;
    else if (i < poolN + NG) g_cnt[i - poolN] = 0.0f;
    if (i == 0) g_is64 = (batch32[n - 1] == 0) ? 1 : 0;
}

__global__ void kPrep(const float* __restrict__ W1, const float* __restrict__ W2,
                      const float* __restrict__ W3) {
    int i = blockIdx.x * 256 + threadIdx.x;
    if (i < 3 * 16384) {
        int widx = i >> 14, e = i & 16383;
        int nn = e >> 7, kk = e & 127;
        const float* W = (widx == 0) ? W1 : (widx == 1) ? W2 : W3;
        float w = W[kk * 128 + nn];
        __nv_bfloat16 h = __float2bfloat16_rn(w);
        g_WTh[i] = h;
        g_WTl[i] = __float2bfloat16_rn(w - __bfloat162float(h));
    }
}

// ---------------------------------------------------------------------------
// kAtomTC: persistent, 512 threads. s = silu(feat@W1+b1) -> segment reduce;
// feat passthrough. cp.async fp32 stage overlaps the mma.
// ---------------------------------------------------------------------------
__device__ __forceinline__ void stage_tile(char* sm, const float* feat, long long tile,
                                           long long n, int t) {
    const int mb = t >> 5, c = t & 31;
    #pragma unroll
    for (int j = 0; j < 8; j++) {
        const int m = mb + j * 16;
        long long row = tile * 128 + m;
        uint32_t dst = smem_u32(sm + SM_STAGE + m * 512 + c * 16);
        const float* src = feat + (size_t)(row < n ? row : 0) * 128 + c * 4;
        cp16(dst, src, row < n ? 16 : 0);
    }
    cp_commit();
}

__global__ void __launch_bounds__(512, 1) kAtomTC(
    const float* __restrict__ feat, const void* __restrict__ batch, int n,
    const float* __restrict__ b1, float* __restrict__ outFeat, int ntiles)
{
    extern __shared__ char sm[];
    const uint32_t smb = smem_u32(sm);
    const int t = threadIdx.x, lane = t & 31, w = t >> 5;
    const int wm = w >> 1, wn = w & 1;
    const int is64 = g_is64;
    const int mb = t >> 5, c = t & 31;

    const int per = (ntiles + gridDim.x - 1) / gridDim.x;
    const int t0 = blockIdx.x * per;
    const int t1 = min(t0 + per, ntiles);
    if (t0 >= t1) return;

    stage_tile(sm, feat, t0, n, t);          // prologue cp.async
    if (t < 128) ((float*)(sm + SM_B1))[t] = b1[t];
    stage_W(sm, SM_W, 0, t);
    cp_wait0();
    __syncthreads();

    for (int i = t0; i < t1; ++i) {
        const bool more = (i + 1 < t1);

        // 1) convert stage -> bf16 hi/lo + passthrough STG + gids
        #pragma unroll
        for (int j = 0; j < 8; j++) {
            const int m = mb + j * 16;
            float4 x = *(const float4*)(sm + SM_STAGE + m * 512 + c * 16);
            split_store(x, sm + SM_A, m, c);
            long long row = (long long)i * 128 + m;
            if (row < n) ((float4*)(outFeat + (size_t)row * 128))[c] = x;
        }
        if (t < 128) {
            long long row = (long long)i * 128 + t;
            int g = -1;
            if (row < n)
                g = is64 ? (int)((const long long*)batch)[row] : ((const int*)batch)[row];
            ((int*)(sm + SM_GID))[t] = g;
        }
        __syncthreads();

        // 2) prefetch next tile (overlaps mma)
        if (more) stage_tile(sm, feat, (long long)i + 1, n, t);

        // 3) mma
        float acc[4][8];
        #pragma unroll
        for (int a = 0; a < 4; a++)
            #pragma unroll
            for (int b = 0; b < 8; b++) acc[a][b] = 0.0f;
        mma_3pass(smb + SM_A, smb + SM_A + 34816, smb + SM_W, smb + SM_W + 34816, acc);
        __syncthreads();   // all warps done reading A

        // 4) epilogue: bias + silu -> transposed sT (stride 129) in A region
        float* sT = (float*)(sm + SM_A);
        const float* sB1 = (const float*)(sm + SM_B1);
        #pragma unroll
        for (int nb = 0; nb < 4; nb++) {
            #pragma unroll
            for (int g = 0; g < 2; g++) {
                const int n0 = wn * 64 + nb * 16 + g * 8 + (lane & 3) * 2;
                const int r0 = wm * 16 + (lane >> 2);
                #pragma unroll
                for (int j = 0; j < 4; j++) {
                    const int nn = n0 + (j & 1);
                    const int mm = r0 + (j >> 1) * 8;
                    float x = acc[nb][g * 4 + j] + sB1[nn];
                    sT[nn * 129 + mm] = x / (1.0f + __expf(-x));
                }
            }
        }
        cp_wait0();
        __syncthreads();

        // 5) run-length segment reduce (batch sorted); 4 quarters of 32 atoms
        const int d = t & 127, hh = t >> 7;
        const int mS = hh * 32, mE = mS + 32;
        const int* gid = (const int*)(sm + SM_GID);
        float run = 0.0f;
        int len = 0, cur = gid[mS];
        for (int mm = mS; mm < mE; ++mm) {
            int g = gid[mm];
            if (g != cur) {
                if (cur >= 0) {
                    atomicAdd(&g_pool[(size_t)cur * 128 + d], run);
                    if (d == 0) atomicAdd(&g_cnt[cur], (float)len);
                }
                run = 0.0f; len = 0; cur = g;
            }
            if (g >= 0) { run += sT[d * 129 + mm]; len++; }
        }
        if (cur >= 0) {
            atomicAdd(&g_pool[(size_t)cur * 128 + d], run);
            if (d == 0) atomicAdd(&g_cnt[cur], (float)len);
        }
        __syncthreads();   // reduce done before next convert overwrites sT/A
    }
}

// ---------------------------------------------------------------------------
// kGraph1: g_pool2 = g_pool @ W2 + cnt * b2   (512 threads, 128-row tiles)
// ---------------------------------------------------------------------------
__global__ void __launch_bounds__(512, 1) kGraph1(const float* __restrict__ b2)
{
    extern __shared__ char sm[];
    const uint32_t smb = smem_u32(sm);
    const int t = threadIdx.x, lane = t & 31, w = t >> 5;
    const int wm = w >> 1, wn = w & 1;
    const int a0 = blockIdx.x * 128;
    const int mb = t >> 5, c = t & 31;

    float* sCnt = (float*)(sm + GS_C);
    float* sB   = (float*)(sm + GS_B);
    if (t < 128) {
        sCnt[t] = (a0 + t < NG) ? g_cnt[a0 + t] : 0.0f;
        sB[t] = b2[t];
    }
    stage_W(sm, GS_W, 1, t);
    #pragma unroll
    for (int j = 0; j < 8; j++) {
        const int m = mb + j * 16;
        int row = a0 + m;
        float4 x = (row < NG) ? ((const float4*)(g_pool + (size_t)row * 128))[c]
                              : make_float4(0.f, 0.f, 0.f, 0.f);
        split_store(x, sm + GS_A, m, c);
    }
    __syncthreads();

    float acc[4][8];
    #pragma unroll
    for (int a = 0; a < 4; a++)
        #pragma unroll
        for (int b = 0; b < 8; b++) acc[a][b] = 0.0f;
    mma_3pass(smb + GS_A, smb + GS_A + 34816, smb + GS_W, smb + GS_W + 34816, acc);

    #pragma unroll
    for (int nb = 0; nb < 4; nb++) {
        #pragma unroll
        for (int g = 0; g < 2; g++) {
            const int n0 = wn * 64 + nb * 16 + g * 8 + (lane & 3) * 2;
            const int mr = wm * 16 + (lane >> 2);
            int row0 = a0 + mr, row1 = a0 + mr + 8;
            if (row0 < NG) {
                float cn = sCnt[mr];
                *(float2*)(g_pool2 + (size_t)row0 * 128 + n0) =
                    make_float2(acc[nb][g*4+0] + cn * sB[n0], acc[nb][g*4+1] + cn * sB[n0+1]);
            }
            if (row1 < NG) {
                float cn = sCnt[mr + 8];
                *(float2*)(g_pool2 + (size_t)row1 * 128 + n0) =
                    make_float2(acc[nb][g*4+2] + cn * sB[n0], acc[nb][g*4+3] + cn * sB[n0+1]);
            }
        }
    }
}

// ---------------------------------------------------------------------------
// kGraph2: out = silu(g_pool2 @ W3 + b3) @ W4 + b4
// ---------------------------------------------------------------------------
__global__ void __launch_bounds__(512, 1) kGraph2(
    const float* __restrict__ b3, const float* __restrict__ W4,
    const float* __restrict__ b4, float* __restrict__ outS)
{
    extern __shared__ char sm[];
    const uint32_t smb = smem_u32(sm);
    const int t = threadIdx.x, lane = t & 31, w = t >> 5;
    const int wm = w >> 1, wn = w & 1;
    const int a0 = blockIdx.x * 128;
    const int mb = t >> 5, c = t & 31;

    float* sV = (float*)(sm + GS_C);
    float* sB = (float*)(sm + GS_B);
    float* sP = (float*)(sm + GS_P);   // partials [2][128]
    if (t < 128) { sV[t] = W4[t]; sB[t] = b3[t]; }
    stage_W(sm, GS_W, 2, t);
    #pragma unroll
    for (int j = 0; j < 8; j++) {
        const int m = mb + j * 16;
        int row = a0 + m;
        float4 x = (row < NG) ? ((const float4*)(g_pool2 + (size_t)row * 128))[c]
                              : make_float4(0.f, 0.f, 0.f, 0.f);
        split_store(x, sm + GS_A, m, c);
    }
    __syncthreads();

    float acc[4][8];
    #pragma unroll
    for (int a = 0; a < 4; a++)
        #pragma unroll
        for (int b = 0; b < 8; b++) acc[a][b] = 0.0f;
    mma_3pass(smb + GS_A, smb + GS_A + 34816, smb + GS_W, smb + GS_W + 34816, acc);

    float s0 = 0.0f, s1 = 0.0f;
    #pragma unroll
    for (int nb = 0; nb < 4; nb++) {
        #pragma unroll
        for (int g = 0; g < 2; g++) {
            const int n0 = wn * 64 + nb * 16 + g * 8 + (lane & 3) * 2;
            #pragma unroll
            for (int j = 0; j < 4; j++) {
                const int nn = n0 + (j & 1);
                float x = acc[nb][g * 4 + j] + sB[nn];
                float h = x / (1.0f + __expf(-x));
                float p = h * sV[nn];
                if (j < 2) s0 += p; else s1 += p;
            }
        }
    }
    s0 += __shfl_xor_sync(0xFFFFFFFF, s0, 1);
    s0 += __shfl_xor_sync(0xFFFFFFFF, s0, 2);
    s1 += __shfl_xor_sync(0xFFFFFFFF, s1, 1);
    s1 += __shfl_xor_sync(0xFFFFFFFF, s1, 2);
    if ((lane & 3) == 0) {
        const int mr = wm * 16 + (lane >> 2);
        sP[wn * 128 + mr] = s0;
        sP[wn * 128 + mr + 8] = s1;
    }
    __syncthreads();
    if (t < 128) {
        int row = a0 + t;
        if (row < NG) outS[row] = sP[t] + sP[128 + t] + b4[0];
    }
}

// ---------------------------------------------------------------------------
extern "C" void kernel_launch(void* const* d_in, const int* in_sizes, int n_in,
                              void* d_out, int out_size)
{
    const float* feat  = (const float*)d_in[0];
    const void*  batch = d_in[1];
    const float* W1 = (const float*)d_in[2];
    const float* b1 = (const float*)d_in[3];
    const float* W2 = (const float*)d_in[4];
    const float* b2 = (const float*)d_in[5];
    const float* W3 = (const float*)d_in[6];
    const float* b3 = (const float*)d_in[7];
    const float* W4 = (const float*)d_in[8];
    const float* b4 = (const float*)d_in[9];

    const int n = in_sizes[0] / DIMW;
    float* outS    = (float*)d_out;
    float* outFeat = (float*)d_out + NG;

    cudaFuncSetAttribute(kAtomTC, cudaFuncAttributeMaxDynamicSharedMemorySize, SMEM_ATOM);
    cudaFuncSetAttribute(kGraph1, cudaFuncAttributeMaxDynamicSharedMemorySize, SMEM_GRAPH);
    cudaFuncSetAttribute(kGraph2, cudaFuncAttributeMaxDynamicSharedMemorySize, SMEM_GRAPH);

    {
        size_t total = (size_t)NG * DIMW + NG;
        kZero<<<(int)((total + 255) / 256), 256>>>((const int*)batch, n);
    }
    kPrep<<<192, 256>>>(W1, W2, W3);
    {
        int ntiles = (n + 127) / 128;
        kAtomTC<<<148, 512, SMEM_ATOM>>>(feat, batch, n, b1, outFeat, ntiles);
    }
    {
        int grid = (NG + 127) / 128;
        kGraph1<<<grid, 512, SMEM_GRAPH>>>(b2);
        kGraph2<<<grid, 512, SMEM_GRAPH>>>(b3, W4, b4, outS);
    }
}